// round 14
// baseline (speedup 1.0000x reference)
#include <cuda_runtime.h>
#include <cuda_fp16.h>
#include <math.h>
#include <stdint.h>

#define NTOK 16384
#define DD   1024
#define CC   256
#define BATCH 64
#define NSEQ 256
#define NEXP 16
#define HH   256

// ---------------- scratch ----------------------------------------------------
__device__ __half g_xn_h[NTOK * DD];
__device__ float  g_rnorm[NTOK];
__device__ float  g_cinv[CC];
__device__ float  g_logits[NTOK * CC];
__device__ __half g_dispT_h[BATCH * CC * NSEQ];
__device__ __half g_comb_h[NTOK * CC];
__device__ __half g_slot_h[BATCH * CC * DD];
__device__ __half g_hh[NEXP * 1024 * HH];
__device__ __half g_mur_h[DD * CC];
__device__ __half g_w1_h[NEXP * DD * HH];
__device__ __half g_w2_h[NEXP * HH * DD];

// ---------------- helpers ----------------------------------------------------
__device__ __forceinline__ uint32_t smem_u32(const void* p) {
    uint32_t a;
    asm("{ .reg .u64 t; cvta.to.shared.u64 t, %1; cvt.u32.u64 %0, t; }" : "=r"(a) : "l"(p));
    return a;
}
__device__ __forceinline__ void cpa16(uint32_t dst, const void* src) {
    asm volatile("cp.async.cg.shared.global [%0], [%1], 16;" :: "r"(dst), "l"(src));
}
#define CP_COMMIT() asm volatile("cp.async.commit_group;" ::: "memory")
#define CP_WAIT2()  asm volatile("cp.async.wait_group 2;" ::: "memory")

__device__ __forceinline__ void ldsm4(uint32_t* r, uint32_t addr) {
    asm volatile("ldmatrix.sync.aligned.m8n8.x4.shared.b16 {%0,%1,%2,%3}, [%4];"
                 : "=r"(r[0]), "=r"(r[1]), "=r"(r[2]), "=r"(r[3]) : "r"(addr));
}
__device__ __forceinline__ void ldsm4t(uint32_t* r, uint32_t addr) {
    asm volatile("ldmatrix.sync.aligned.m8n8.x4.trans.shared.b16 {%0,%1,%2,%3}, [%4];"
                 : "=r"(r[0]), "=r"(r[1]), "=r"(r[2]), "=r"(r[3]) : "r"(addr));
}
__device__ __forceinline__ void mma_f16(float* d, const uint32_t* a, const uint32_t* b) {
    asm volatile(
        "mma.sync.aligned.m16n8k16.row.col.f32.f16.f16.f32 "
        "{%0,%1,%2,%3}, {%4,%5,%6,%7}, {%8,%9}, {%0,%1,%2,%3};"
        : "+f"(d[0]), "+f"(d[1]), "+f"(d[2]), "+f"(d[3])
        : "r"(a[0]), "r"(a[1]), "r"(a[2]), "r"(a[3]), "r"(b[0]), "r"(b[1]));
}

// ---------------- fp32 -> fp16 conversion (MLP 8) ------------------------------
__global__ void half_copy(const float* __restrict__ src, __half* __restrict__ dst) {
    int i = blockIdx.x * 2048 + threadIdx.x;
    float4 v[8];
#pragma unroll
    for (int j = 0; j < 8; j++) v[j] = ((const float4*)src)[i + j * 256];
#pragma unroll
    for (int j = 0; j < 8; j++) {
        int o = i + j * 256;
        ((__half2*)dst)[2 * o]     = __floats2half2_rn(v[j].x, v[j].y);
        ((__half2*)dst)[2 * o + 1] = __floats2half2_rn(v[j].z, v[j].w);
    }
}

// ---------------- fused mu prep: column norms + fp16 convert -------------------
__global__ void mu_prep(const float* __restrict__ mu, __half* __restrict__ dst) {
    int c0 = blockIdx.x * 32;
    int tid = threadIdx.x;
    int c = tid & 31, rg = tid >> 5;
    float s = 0.f;
    for (int r = rg; r < DD; r += 8) {
        float v = mu[r * CC + c0 + c];
        s += v * v;
        dst[r * CC + c0 + c] = __float2half_rn(v);
    }
    __shared__ float red[8][33];
    red[rg][c] = s;
    __syncthreads();
    if (rg == 0) {
        float t = 0.f;
#pragma unroll
        for (int j = 0; j < 8; j++) t += red[j][c];
        g_cinv[c0 + c] = 1.f / fmaxf(sqrtf(t), 1e-12f);
    }
}

// ---------------- LayerNorm: warp per token, MLP 8 -----------------------------
__global__ void ln_kernel(const float* __restrict__ x,
                          const float* __restrict__ gamma,
                          const float* __restrict__ beta, int off) {
    int lane = threadIdx.x & 31;
    int t = (blockIdx.x + off) * 8 + (threadIdx.x >> 5);
    const float4* xr = (const float4*)(x + (size_t)t * DD);

    float4 v[8];
#pragma unroll
    for (int j = 0; j < 8; j++) v[j] = xr[lane + 32 * j];

    float s = 0.f, ss = 0.f;
#pragma unroll
    for (int j = 0; j < 8; j++) {
        s  += v[j].x + v[j].y + v[j].z + v[j].w;
        ss += v[j].x * v[j].x + v[j].y * v[j].y + v[j].z * v[j].z + v[j].w * v[j].w;
    }
    for (int o = 16; o > 0; o >>= 1) {
        s  += __shfl_xor_sync(0xffffffffu, s, o);
        ss += __shfl_xor_sync(0xffffffffu, ss, o);
    }
    float mean = s * (1.f / DD);
    float var  = ss * (1.f / DD) - mean * mean;
    float rstd = rsqrtf(var + 1e-5f);

    __half2* yr = (__half2*)(g_xn_h + (size_t)t * DD);
    float s2 = 0.f;
#pragma unroll
    for (int j = 0; j < 8; j++) {
        int i = lane + 32 * j;
        float4 g = ((const float4*)gamma)[i];
        float4 b = ((const float4*)beta)[i];
        __half2 h01 = __floats2half2_rn((v[j].x - mean) * rstd * g.x + b.x,
                                        (v[j].y - mean) * rstd * g.y + b.y);
        __half2 h23 = __floats2half2_rn((v[j].z - mean) * rstd * g.z + b.z,
                                        (v[j].w - mean) * rstd * g.w + b.w);
        yr[2 * i] = h01; yr[2 * i + 1] = h23;
        float2 f01 = __half22float2(h01), f23 = __half22float2(h23);
        s2 += f01.x * f01.x + f01.y * f01.y + f23.x * f23.x + f23.y * f23.y;
    }
    for (int o = 16; o > 0; o >>= 1) s2 += __shfl_xor_sync(0xffffffffu, s2, o);
    if (lane == 0) g_rnorm[t] = 1.f / fmaxf(sqrtf(s2), 1e-12f);
}

// ---------------- combine softmax ----------------------------------------------
__global__ void combine_kernel() {
    int row = blockIdx.x * 8 + threadIdx.y;
    int lane = threadIdx.x;
    const float* lr = g_logits + (size_t)row * CC;
    float v[8]; float mx = -1e30f;
#pragma unroll
    for (int j = 0; j < 8; j++) { v[j] = lr[lane + 32 * j]; mx = fmaxf(mx, v[j]); }
    for (int o = 16; o > 0; o >>= 1) mx = fmaxf(mx, __shfl_xor_sync(0xffffffffu, mx, o));
    float s = 0.f;
#pragma unroll
    for (int j = 0; j < 8; j++) { v[j] = __expf(v[j] - mx); s += v[j]; }
    for (int o = 16; o > 0; o >>= 1) s += __shfl_xor_sync(0xffffffffu, s, o);
    float inv = 1.f / s;
    __half* cr = g_comb_h + (size_t)row * CC;
#pragma unroll
    for (int j = 0; j < 8; j++) cr[lane + 32 * j] = __float2half_rn(v[j] * inv);
}

// ---------------- dispatch softmax; transposed fp16 output ----------------------
__global__ void dispatch_kernel(int boff) {
    int b = blockIdx.y + boff, c0 = blockIdx.x * 32, tid = threadIdx.x;
    int c = tid & 31, nb = tid >> 5;
    __shared__ float tile[256][33];
    __shared__ float pred[8][32];
    __shared__ float colv[32];

    const size_t base = ((size_t)b * NSEQ) * CC + c0;
#pragma unroll
    for (int it = 0; it < 32; it++) {
        int n = nb + 8 * it;
        tile[n][c] = g_logits[base + (size_t)n * CC + c];
    }
    __syncthreads();
    float mx = -1e30f;
#pragma unroll
    for (int j = 0; j < 32; j++) mx = fmaxf(mx, tile[nb * 32 + j][c]);
    pred[nb][c] = mx; __syncthreads();
    if (nb == 0) {
        float m = pred[0][c];
#pragma unroll
        for (int j = 1; j < 8; j++) m = fmaxf(m, pred[j][c]);
        colv[c] = m;
    }
    __syncthreads();
    float cm = colv[c];
    float s = 0.f;
#pragma unroll
    for (int j = 0; j < 32; j++) {
        float e = __expf(tile[nb * 32 + j][c] - cm);
        tile[nb * 32 + j][c] = e; s += e;
    }
    pred[nb][c] = s; __syncthreads();
    if (nb == 0) {
        float t = 0.f;
#pragma unroll
        for (int j = 0; j < 8; j++) t += pred[j][c];
        colv[c] = 1.f / t;
    }
    __syncthreads();
    int lane2 = tid & 31, cg = tid >> 5;
#pragma unroll
    for (int cc2 = 0; cc2 < 4; cc2++) {
        int cl = cg + 8 * cc2;
        float inv = colv[cl];
        size_t ob = ((size_t)b * CC + c0 + cl) * NSEQ;
#pragma unroll
        for (int itn = 0; itn < 8; itn++) {
            int n = lane2 + 32 * itn;
            g_dispT_h[ob + n] = __float2half_rn(tile[n][cl] * inv);
        }
    }
}

// ---------------- fp16 mma GEMM, CTA 128x128, occ 2, cp.async 4-stage -----------
// Issue-before-compute: stage s+3 cp.asyncs are issued BEFORE computing stage s.
#define STG_B 18944
#define B_OFF 10240

template <int MODE>
__global__ void __launch_bounds__(256, 2) gemm_h(const float* __restrict__ X2,
                                                 float* __restrict__ Cout,
                                                 const float* __restrict__ sp,
                                                 int off) {
    constexpr int Kx  = (MODE == 0 || MODE == 2) ? 1024 : 256;
    constexpr int ldb = (MODE == 0 || MODE == 2) ? 256 : 1024;
    constexpr int lda = (MODE == 0 || MODE == 2) ? 1024 : 256;
    constexpr int NC  = Kx / 32;

    extern __shared__ __half sm[];
    const uint32_t sb = smem_u32(sm);
    const int tid = threadIdx.x, wid = tid >> 5, lane = tid & 31;
    const int warp_m = wid & 1, warp_n = wid >> 1;
    const int r = lane >> 2, t = lane & 3;
    const int z  = (MODE == 0) ? 0 : (blockIdx.z + ((MODE == 4) ? 0 : off));
    const int m0 = ((MODE == 0) ? (blockIdx.y + off) : blockIdx.y) * 128;
    const int n0 = blockIdx.x * 128;

    const __half* Abase;
    const __half* Bbase;
    if (MODE == 0)      { Abase = g_xn_h + (size_t)m0 * 1024;                        Bbase = g_mur_h; }
    else if (MODE == 1) { Abase = g_dispT_h + ((size_t)z << 16) + (size_t)m0 * 256;  Bbase = g_xn_h + ((size_t)z << 18); }
    else if (MODE == 2) { Abase = g_slot_h;                                          Bbase = g_w1_h + ((size_t)z << 18); }
    else if (MODE == 3) { Abase = g_hh + ((size_t)z << 18) + (size_t)m0 * 256;       Bbase = g_w2_h + ((size_t)z << 18); }
    else                { Abase = g_comb_h + ((size_t)z << 16) + (size_t)m0 * 256;   Bbase = g_slot_h + ((size_t)z << 18); }

    const int am  = tid >> 1;
    const int akh = (tid & 1) * 16;
    const int bk  = tid >> 3;
    const int bn8 = (tid & 7) * 8;
    const __half* arow;
    if (MODE == 2) {
        int g = m0 + am;
        arow = g_slot_h + (size_t)(((g >> 4) << 8) + (z << 4) + (g & 15)) * 1024;
    } else {
        arow = Abase + (size_t)am * lda;
    }
    const __half* brow = Bbase + n0 + bn8;
    const uint32_t a_dst0 = sb + am * 80 + akh * 2;
    const uint32_t b_dst0 = sb + B_OFF + bk * 272 + bn8 * 2;

    float acc[4][4][4];
#pragma unroll
    for (int mt = 0; mt < 4; mt++)
#pragma unroll
        for (int nt = 0; nt < 4; nt++)
#pragma unroll
            for (int q = 0; q < 4; q++) acc[mt][nt][q] = 0.f;

    // prologue: stages 0..2
#pragma unroll
    for (int stg = 0; stg < 3; stg++) {
        const int k0 = stg * 32;
#pragma unroll
        for (int i = 0; i < 2; i++)
            cpa16(a_dst0 + stg * STG_B + i * 16, arow + k0 + akh + i * 8);
#pragma unroll
        for (int i = 0; i < 2; i++)
            cpa16(b_dst0 + stg * STG_B + i * 128, brow + (size_t)(k0 + bk) * ldb + i * 64);
        CP_COMMIT();
    }

    int st = 0;
#pragma unroll 1
    for (int s = 0; s < NC; s++) {
        CP_WAIT2();
        __syncthreads();

        // issue stage s+3 FIRST (WAR-safe: buffer (s+3)&3 was consumed at s-1,
        // and the sync above guarantees all warps are past it)
        if (s + 3 < NC) {
            const int ld = (s + 3) & 3;
            const int k0 = (s + 3) * 32;
#pragma unroll
            for (int i = 0; i < 2; i++)
                cpa16(a_dst0 + ld * STG_B + i * 16, arow + k0 + akh + i * 8);
#pragma unroll
            for (int i = 0; i < 2; i++)
                cpa16(b_dst0 + ld * STG_B + i * 128, brow + (size_t)(k0 + bk) * ldb + i * 64);
        }
        CP_COMMIT();

        // compute stage st
        {
            const uint32_t base = sb + st * STG_B;
            const uint32_t a_ld = base + (warp_m * 64 + (lane & 15)) * 80 + (lane >> 4) * 16;
            const uint32_t b_ld = base + B_OFF + (((lane >> 3) & 1) * 8 + (lane & 7)) * 272
                                  + (warp_n * 32 + (lane >> 4) * 8) * 2;
#pragma unroll
            for (int ks = 0; ks < 2; ks++) {
                uint32_t a[4][4], b[4][2];
#pragma unroll
                for (int mt = 0; mt < 4; mt++)
                    ldsm4(a[mt], a_ld + mt * (16 * 80) + ks * 32);
#pragma unroll
                for (int ntp = 0; ntp < 2; ntp++) {
                    uint32_t bbf[4];
                    ldsm4t(bbf, b_ld + ks * (16 * 272) + ntp * 32);
                    b[2 * ntp][0] = bbf[0]; b[2 * ntp][1] = bbf[1];
                    b[2 * ntp + 1][0] = bbf[2]; b[2 * ntp + 1][1] = bbf[3];
                }
#pragma unroll
                for (int mt = 0; mt < 4; mt++)
#pragma unroll
                    for (int nt = 0; nt < 4; nt++)
                        mma_f16(acc[mt][nt], a[mt], b[nt]);
            }
        }
        st = (st + 1) & 3;
    }

    // ---- epilogue
    float spv = (MODE == 0) ? sp[0] : 0.f;
#pragma unroll
    for (int mt = 0; mt < 4; mt++) {
        int row = m0 + warp_m * 64 + mt * 16 + r;
#pragma unroll
        for (int hf = 0; hf < 2; hf++) {
            int rw = row + hf * 8;
            float rs0 = 0.f;
            if (MODE == 0) rs0 = spv * g_rnorm[rw];
#pragma unroll
            for (int nt = 0; nt < 4; nt++) {
                int col = n0 + warp_n * 32 + nt * 8 + 2 * t;
                float v0 = acc[mt][nt][hf * 2 + 0];
                float v1 = acc[mt][nt][hf * 2 + 1];
                if (MODE == 0) {
                    v0 *= rs0 * g_cinv[col];
                    v1 *= rs0 * g_cinv[col + 1];
                    *(float2*)(g_logits + (size_t)rw * 256 + col) = make_float2(v0, v1);
                } else if (MODE == 1) {
                    __half* orow = g_slot_h + (((size_t)z << 8) + rw) * 1024;
                    *(__half2*)(orow + col) = __floats2half2_rn(v0, v1);
                } else if (MODE == 2) {
                    v0 += X2[(z << 8) + col];
                    v1 += X2[(z << 8) + col + 1];
                    v0 = 0.5f * v0 * (1.f + erff(v0 * 0.70710678118654752f));
                    v1 = 0.5f * v1 * (1.f + erff(v1 * 0.70710678118654752f));
                    __half* orow = g_hh + (((size_t)z << 10) + rw) * 256;
                    *(__half2*)(orow + col) = __floats2half2_rn(v0, v1);
                } else if (MODE == 3) {
                    v0 += X2[(z << 10) + col];
                    v1 += X2[(z << 10) + col + 1];
                    int rr = ((rw >> 4) << 8) + (z << 4) + (rw & 15);
                    __half* orow = g_slot_h + (size_t)rr * 1024;
                    *(__half2*)(orow + col) = __floats2half2_rn(v0, v1);
                } else {
                    *(float2*)(Cout + (((size_t)z << 8) + rw) * 1024 + col) = make_float2(v0, v1);
                }
            }
        }
    }
}

// ---------------- launch --------------------------------------------------------
static const int GEMM_SMEM = 4 * STG_B;   // 75,776 bytes -> 2 CTAs/SM

extern "C" void kernel_launch(void* const* d_in, const int* in_sizes, int n_in,
                              void* d_out, int out_size) {
    const float* x     = (const float*)d_in[0];
    const float* gamma = (const float*)d_in[1];
    const float* beta  = (const float*)d_in[2];
    const float* mu    = (const float*)d_in[3];
    const float* scale = (const float*)d_in[4];
    const float* w1    = (const float*)d_in[5];
    const float* b1    = (const float*)d_in[6];
    const float* w2    = (const float*)d_in[7];
    const float* b2    = (const float*)d_in[8];
    float* out = (float*)d_out;

    static cudaStream_t s1 = nullptr, s2 = nullptr, s3 = nullptr;
    static cudaEvent_t eA, e1, e2, e3, eG0a, eG0b, eG1a, eG1b, eG3b;
    static int init_done = 0;
    if (!init_done) {
        cudaStreamCreateWithFlags(&s1, cudaStreamNonBlocking);
        cudaStreamCreateWithFlags(&s2, cudaStreamNonBlocking);
        cudaStreamCreateWithFlags(&s3, cudaStreamNonBlocking);
        cudaEventCreateWithFlags(&eA,  cudaEventDisableTiming);
        cudaEventCreateWithFlags(&e1,  cudaEventDisableTiming);
        cudaEventCreateWithFlags(&e2,  cudaEventDisableTiming);
        cudaEventCreateWithFlags(&e3,  cudaEventDisableTiming);
        cudaEventCreateWithFlags(&eG0a, cudaEventDisableTiming);
        cudaEventCreateWithFlags(&eG0b, cudaEventDisableTiming);
        cudaEventCreateWithFlags(&eG1a, cudaEventDisableTiming);
        cudaEventCreateWithFlags(&eG1b, cudaEventDisableTiming);
        cudaEventCreateWithFlags(&eG3b, cudaEventDisableTiming);
        cudaFuncSetAttribute(gemm_h<0>, cudaFuncAttributeMaxDynamicSharedMemorySize, GEMM_SMEM);
        cudaFuncSetAttribute(gemm_h<1>, cudaFuncAttributeMaxDynamicSharedMemorySize, GEMM_SMEM);
        cudaFuncSetAttribute(gemm_h<2>, cudaFuncAttributeMaxDynamicSharedMemorySize, GEMM_SMEM);
        cudaFuncSetAttribute(gemm_h<3>, cudaFuncAttributeMaxDynamicSharedMemorySize, GEMM_SMEM);
        cudaFuncSetAttribute(gemm_h<4>, cudaFuncAttributeMaxDynamicSharedMemorySize, GEMM_SMEM);
        init_done = 1;
    }

    __half* mur_p; cudaGetSymbolAddress((void**)&mur_p, g_mur_h);
    __half* w1_p;  cudaGetSymbolAddress((void**)&w1_p,  g_w1_h);
    __half* w2_p;  cudaGetSymbolAddress((void**)&w2_p,  g_w2_h);

    // fork
    cudaEventRecord(eA, 0);
    cudaStreamWaitEvent(s1, eA, 0);
    cudaStreamWaitEvent(s2, eA, 0);
    cudaStreamWaitEvent(s3, eA, 0);

    // s1: weight conversions
    half_copy<<<NEXP * DD * HH / 8192, 256, 0, s1>>>(w1, w1_p);
    half_copy<<<NEXP * HH * DD / 8192, 256, 0, s1>>>(w2, w2_p);
    cudaEventRecord(e1, s1);

    // s2: fused mu prep (norms + fp16 convert)
    mu_prep<<<8, 256, 0, s2>>>(mu, mur_p);
    cudaEventRecord(e2, s2);

    // s0: ln first half, s3: second half
    ln_kernel<<<1024, 256>>>(x, gamma, beta, 0);
    ln_kernel<<<1024, 256, 0, s3>>>(x, gamma, beta, 1024);

    // G0 halves — each needs its ln half + mu prep
    cudaStreamWaitEvent(0, e2, 0);
    gemm_h<0><<<dim3(2, 64, 1), 256, GEMM_SMEM>>>(nullptr, nullptr, scale, 0);
    cudaEventRecord(eG0a, 0);
    cudaStreamWaitEvent(s3, e2, 0);
    gemm_h<0><<<dim3(2, 64, 1), 256, GEMM_SMEM, s3>>>(nullptr, nullptr, scale, 64);
    cudaEventRecord(eG0b, s3);

    // combine (s2) after both logits halves
    cudaStreamWaitEvent(s2, eG0a, 0);
    cudaStreamWaitEvent(s2, eG0b, 0);
    combine_kernel<<<NTOK / 8, dim3(32, 8), 0, s2>>>();
    cudaEventRecord(e3, s2);

    // dispatch + G1 per batch half
    dispatch_kernel<<<dim3(8, 32), 256>>>(0);
    gemm_h<1><<<dim3(8, 2, 32), 256, GEMM_SMEM>>>(nullptr, nullptr, nullptr, 0);
    cudaEventRecord(eG1a, 0);

    dispatch_kernel<<<dim3(8, 32), 256, 0, s3>>>(32);
    gemm_h<1><<<dim3(8, 2, 32), 256, GEMM_SMEM, s3>>>(nullptr, nullptr, nullptr, 32);
    cudaEventRecord(eG1b, s3);

    // G2/G3 per expert half; each needs ALL of G1 + weights
    cudaStreamWaitEvent(0, e1, 0);
    cudaStreamWaitEvent(0, eG1b, 0);
    gemm_h<2><<<dim3(2, 8, 8), 256, GEMM_SMEM>>>(b1, nullptr, nullptr, 0);
    gemm_h<3><<<dim3(8, 8, 8), 256, GEMM_SMEM>>>(b2, nullptr, nullptr, 0);

    cudaStreamWaitEvent(s3, e1, 0);
    cudaStreamWaitEvent(s3, eG1a, 0);
    gemm_h<2><<<dim3(2, 8, 8), 256, GEMM_SMEM, s3>>>(b1, nullptr, nullptr, 8);
    gemm_h<3><<<dim3(8, 8, 8), 256, GEMM_SMEM, s3>>>(b2, nullptr, nullptr, 8);
    cudaEventRecord(eG3b, s3);

    // G4 after all slot_out + combine
    cudaStreamWaitEvent(0, eG3b, 0);
    cudaStreamWaitEvent(0, e3, 0);
    gemm_h<4><<<dim3(8, 2, 64), 256, GEMM_SMEM>>>(nullptr, out, nullptr, 0);
}

// round 15
// speedup vs baseline: 1.0582x; 1.0582x over previous
#include <cuda_runtime.h>
#include <cuda_fp16.h>
#include <math.h>
#include <stdint.h>

#define NTOK 16384
#define DD   1024
#define CC   256
#define BATCH 64
#define NSEQ 256
#define NEXP 16
#define HH   256

// ---------------- scratch ----------------------------------------------------
__device__ __half g_xn_h[NTOK * DD];
__device__ float  g_rnorm[NTOK];
__device__ float  g_cinv[CC];
__device__ float  g_logits[NTOK * CC];
__device__ __half g_dispT_h[BATCH * CC * NSEQ];
__device__ __half g_comb_h[NTOK * CC];
__device__ __half g_slot_h[BATCH * CC * DD];
__device__ __half g_hh[NEXP * 1024 * HH];
__device__ __half g_mur_h[DD * CC];
__device__ __half g_w1_h[NEXP * DD * HH];
__device__ __half g_w2_h[NEXP * HH * DD];

// ---------------- helpers ----------------------------------------------------
__device__ __forceinline__ uint32_t smem_u32(const void* p) {
    uint32_t a;
    asm("{ .reg .u64 t; cvta.to.shared.u64 t, %1; cvt.u32.u64 %0, t; }" : "=r"(a) : "l"(p));
    return a;
}
__device__ __forceinline__ void cpa16(uint32_t dst, const void* src) {
    asm volatile("cp.async.cg.shared.global [%0], [%1], 16;" :: "r"(dst), "l"(src));
}
#define CP_COMMIT() asm volatile("cp.async.commit_group;" ::: "memory")
#define CP_WAIT2()  asm volatile("cp.async.wait_group 2;" ::: "memory")

__device__ __forceinline__ void ldsm4(uint32_t* r, uint32_t addr) {
    asm volatile("ldmatrix.sync.aligned.m8n8.x4.shared.b16 {%0,%1,%2,%3}, [%4];"
                 : "=r"(r[0]), "=r"(r[1]), "=r"(r[2]), "=r"(r[3]) : "r"(addr));
}
__device__ __forceinline__ void ldsm4t(uint32_t* r, uint32_t addr) {
    asm volatile("ldmatrix.sync.aligned.m8n8.x4.trans.shared.b16 {%0,%1,%2,%3}, [%4];"
                 : "=r"(r[0]), "=r"(r[1]), "=r"(r[2]), "=r"(r[3]) : "r"(addr));
}
__device__ __forceinline__ void mma_f16(float* d, const uint32_t* a, const uint32_t* b) {
    asm volatile(
        "mma.sync.aligned.m16n8k16.row.col.f32.f16.f16.f32 "
        "{%0,%1,%2,%3}, {%4,%5,%6,%7}, {%8,%9}, {%0,%1,%2,%3};"
        : "+f"(d[0]), "+f"(d[1]), "+f"(d[2]), "+f"(d[3])
        : "r"(a[0]), "r"(a[1]), "r"(a[2]), "r"(a[3]), "r"(b[0]), "r"(b[1]));
}

// ---------------- fp32 -> fp16 conversion (MLP 8) ------------------------------
__global__ void half_copy(const float* __restrict__ src, __half* __restrict__ dst) {
    int i = blockIdx.x * 2048 + threadIdx.x;
    float4 v[8];
#pragma unroll
    for (int j = 0; j < 8; j++) v[j] = ((const float4*)src)[i + j * 256];
#pragma unroll
    for (int j = 0; j < 8; j++) {
        int o = i + j * 256;
        ((__half2*)dst)[2 * o]     = __floats2half2_rn(v[j].x, v[j].y);
        ((__half2*)dst)[2 * o + 1] = __floats2half2_rn(v[j].z, v[j].w);
    }
}

// ---------------- fused mu prep: column norms + fp16 convert -------------------
__global__ void mu_prep(const float* __restrict__ mu, __half* __restrict__ dst) {
    int c0 = blockIdx.x * 32;
    int tid = threadIdx.x;
    int c = tid & 31, rg = tid >> 5;
    float s = 0.f;
    for (int r = rg; r < DD; r += 8) {
        float v = mu[r * CC + c0 + c];
        s += v * v;
        dst[r * CC + c0 + c] = __float2half_rn(v);
    }
    __shared__ float red[8][33];
    red[rg][c] = s;
    __syncthreads();
    if (rg == 0) {
        float t = 0.f;
#pragma unroll
        for (int j = 0; j < 8; j++) t += red[j][c];
        g_cinv[c0 + c] = 1.f / fmaxf(sqrtf(t), 1e-12f);
    }
}

// ---------------- LayerNorm: warp per token, MLP 8 -----------------------------
__global__ void ln_kernel(const float* __restrict__ x,
                          const float* __restrict__ gamma,
                          const float* __restrict__ beta, int off) {
    int lane = threadIdx.x & 31;
    int t = (blockIdx.x + off) * 8 + (threadIdx.x >> 5);
    const float4* xr = (const float4*)(x + (size_t)t * DD);

    float4 v[8];
#pragma unroll
    for (int j = 0; j < 8; j++) v[j] = xr[lane + 32 * j];

    float s = 0.f, ss = 0.f;
#pragma unroll
    for (int j = 0; j < 8; j++) {
        s  += v[j].x + v[j].y + v[j].z + v[j].w;
        ss += v[j].x * v[j].x + v[j].y * v[j].y + v[j].z * v[j].z + v[j].w * v[j].w;
    }
    for (int o = 16; o > 0; o >>= 1) {
        s  += __shfl_xor_sync(0xffffffffu, s, o);
        ss += __shfl_xor_sync(0xffffffffu, ss, o);
    }
    float mean = s * (1.f / DD);
    float var  = ss * (1.f / DD) - mean * mean;
    float rstd = rsqrtf(var + 1e-5f);

    __half2* yr = (__half2*)(g_xn_h + (size_t)t * DD);
    float s2 = 0.f;
#pragma unroll
    for (int j = 0; j < 8; j++) {
        int i = lane + 32 * j;
        float4 g = ((const float4*)gamma)[i];
        float4 b = ((const float4*)beta)[i];
        __half2 h01 = __floats2half2_rn((v[j].x - mean) * rstd * g.x + b.x,
                                        (v[j].y - mean) * rstd * g.y + b.y);
        __half2 h23 = __floats2half2_rn((v[j].z - mean) * rstd * g.z + b.z,
                                        (v[j].w - mean) * rstd * g.w + b.w);
        yr[2 * i] = h01; yr[2 * i + 1] = h23;
        float2 f01 = __half22float2(h01), f23 = __half22float2(h23);
        s2 += f01.x * f01.x + f01.y * f01.y + f23.x * f23.x + f23.y * f23.y;
    }
    for (int o = 16; o > 0; o >>= 1) s2 += __shfl_xor_sync(0xffffffffu, s2, o);
    if (lane == 0) g_rnorm[t] = 1.f / fmaxf(sqrtf(s2), 1e-12f);
}

// ---------------- combine softmax ----------------------------------------------
__global__ void combine_kernel() {
    int row = blockIdx.x * 8 + threadIdx.y;
    int lane = threadIdx.x;
    const float* lr = g_logits + (size_t)row * CC;
    float v[8]; float mx = -1e30f;
#pragma unroll
    for (int j = 0; j < 8; j++) { v[j] = lr[lane + 32 * j]; mx = fmaxf(mx, v[j]); }
    for (int o = 16; o > 0; o >>= 1) mx = fmaxf(mx, __shfl_xor_sync(0xffffffffu, mx, o));
    float s = 0.f;
#pragma unroll
    for (int j = 0; j < 8; j++) { v[j] = __expf(v[j] - mx); s += v[j]; }
    for (int o = 16; o > 0; o >>= 1) s += __shfl_xor_sync(0xffffffffu, s, o);
    float inv = 1.f / s;
    __half* cr = g_comb_h + (size_t)row * CC;
#pragma unroll
    for (int j = 0; j < 8; j++) cr[lane + 32 * j] = __float2half_rn(v[j] * inv);
}

// ---------------- dispatch softmax; transposed fp16 output ----------------------
__global__ void dispatch_kernel(int boff) {
    int b = blockIdx.y + boff, c0 = blockIdx.x * 32, tid = threadIdx.x;
    int c = tid & 31, nb = tid >> 5;
    __shared__ float tile[256][33];
    __shared__ float pred[8][32];
    __shared__ float colv[32];

    const size_t base = ((size_t)b * NSEQ) * CC + c0;
#pragma unroll
    for (int it = 0; it < 32; it++) {
        int n = nb + 8 * it;
        tile[n][c] = g_logits[base + (size_t)n * CC + c];
    }
    __syncthreads();
    float mx = -1e30f;
#pragma unroll
    for (int j = 0; j < 32; j++) mx = fmaxf(mx, tile[nb * 32 + j][c]);
    pred[nb][c] = mx; __syncthreads();
    if (nb == 0) {
        float m = pred[0][c];
#pragma unroll
        for (int j = 1; j < 8; j++) m = fmaxf(m, pred[j][c]);
        colv[c] = m;
    }
    __syncthreads();
    float cm = colv[c];
    float s = 0.f;
#pragma unroll
    for (int j = 0; j < 32; j++) {
        float e = __expf(tile[nb * 32 + j][c] - cm);
        tile[nb * 32 + j][c] = e; s += e;
    }
    pred[nb][c] = s; __syncthreads();
    if (nb == 0) {
        float t = 0.f;
#pragma unroll
        for (int j = 0; j < 8; j++) t += pred[j][c];
        colv[c] = 1.f / t;
    }
    __syncthreads();
    int lane2 = tid & 31, cg = tid >> 5;
#pragma unroll
    for (int cc2 = 0; cc2 < 4; cc2++) {
        int cl = cg + 8 * cc2;
        float inv = colv[cl];
        size_t ob = ((size_t)b * CC + c0 + cl) * NSEQ;
#pragma unroll
        for (int itn = 0; itn < 8; itn++) {
            int n = lane2 + 32 * itn;
            g_dispT_h[ob + n] = __float2half_rn(tile[n][cl] * inv);
        }
    }
}

// ---------------- fp16 mma GEMM, CTA 128x128, occ 2, cp.async 4-stage -----------
// Mainloop order: wait -> sync -> COMPUTE -> issue s+3 -> commit  (R12-proven)
#define STG_B 18944
#define B_OFF 10240

template <int MODE>
__global__ void __launch_bounds__(256, 2) gemm_h(const float* __restrict__ X2,
                                                 float* __restrict__ Cout,
                                                 const float* __restrict__ sp,
                                                 int off) {
    constexpr int Kx  = (MODE == 0 || MODE == 2) ? 1024 : 256;
    constexpr int ldb = (MODE == 0 || MODE == 2) ? 256 : 1024;
    constexpr int lda = (MODE == 0 || MODE == 2) ? 1024 : 256;
    constexpr int NC  = Kx / 32;

    extern __shared__ __half sm[];
    const uint32_t sb = smem_u32(sm);
    const int tid = threadIdx.x, wid = tid >> 5, lane = tid & 31;
    const int warp_m = wid & 1, warp_n = wid >> 1;
    const int r = lane >> 2, t = lane & 3;
    const int z  = (MODE == 0) ? 0 : (blockIdx.z + ((MODE == 4) ? 0 : off));
    const int m0 = ((MODE == 0) ? (blockIdx.y + off) : blockIdx.y) * 128;
    const int n0 = blockIdx.x * 128;

    const __half* Abase;
    const __half* Bbase;
    if (MODE == 0)      { Abase = g_xn_h + (size_t)m0 * 1024;                        Bbase = g_mur_h; }
    else if (MODE == 1) { Abase = g_dispT_h + ((size_t)z << 16) + (size_t)m0 * 256;  Bbase = g_xn_h + ((size_t)z << 18); }
    else if (MODE == 2) { Abase = g_slot_h;                                          Bbase = g_w1_h + ((size_t)z << 18); }
    else if (MODE == 3) { Abase = g_hh + ((size_t)z << 18) + (size_t)m0 * 256;       Bbase = g_w2_h + ((size_t)z << 18); }
    else                { Abase = g_comb_h + ((size_t)z << 16) + (size_t)m0 * 256;   Bbase = g_slot_h + ((size_t)z << 18); }

    const int am  = tid >> 1;
    const int akh = (tid & 1) * 16;
    const int bk  = tid >> 3;
    const int bn8 = (tid & 7) * 8;
    const __half* arow;
    if (MODE == 2) {
        int g = m0 + am;
        arow = g_slot_h + (size_t)(((g >> 4) << 8) + (z << 4) + (g & 15)) * 1024;
    } else {
        arow = Abase + (size_t)am * lda;
    }
    const __half* brow = Bbase + n0 + bn8;
    const uint32_t a_dst0 = sb + am * 80 + akh * 2;
    const uint32_t b_dst0 = sb + B_OFF + bk * 272 + bn8 * 2;

    float acc[4][4][4];
#pragma unroll
    for (int mt = 0; mt < 4; mt++)
#pragma unroll
        for (int nt = 0; nt < 4; nt++)
#pragma unroll
            for (int q = 0; q < 4; q++) acc[mt][nt][q] = 0.f;

    // prologue: stages 0..2
#pragma unroll
    for (int stg = 0; stg < 3; stg++) {
        const int k0 = stg * 32;
#pragma unroll
        for (int i = 0; i < 2; i++)
            cpa16(a_dst0 + stg * STG_B + i * 16, arow + k0 + akh + i * 8);
#pragma unroll
        for (int i = 0; i < 2; i++)
            cpa16(b_dst0 + stg * STG_B + i * 128, brow + (size_t)(k0 + bk) * ldb + i * 64);
        CP_COMMIT();
    }

    int st = 0;
#pragma unroll 1
    for (int s = 0; s < NC; s++) {
        CP_WAIT2();
        __syncthreads();

        // compute stage st
        {
            const uint32_t base = sb + st * STG_B;
            const uint32_t a_ld = base + (warp_m * 64 + (lane & 15)) * 80 + (lane >> 4) * 16;
            const uint32_t b_ld = base + B_OFF + (((lane >> 3) & 1) * 8 + (lane & 7)) * 272
                                  + (warp_n * 32 + (lane >> 4) * 8) * 2;
#pragma unroll
            for (int ks = 0; ks < 2; ks++) {
                uint32_t a[4][4], b[4][2];
#pragma unroll
                for (int mt = 0; mt < 4; mt++)
                    ldsm4(a[mt], a_ld + mt * (16 * 80) + ks * 32);
#pragma unroll
                for (int ntp = 0; ntp < 2; ntp++) {
                    uint32_t bbf[4];
                    ldsm4t(bbf, b_ld + ks * (16 * 272) + ntp * 32);
                    b[2 * ntp][0] = bbf[0]; b[2 * ntp][1] = bbf[1];
                    b[2 * ntp + 1][0] = bbf[2]; b[2 * ntp + 1][1] = bbf[3];
                }
#pragma unroll
                for (int mt = 0; mt < 4; mt++)
#pragma unroll
                    for (int nt = 0; nt < 4; nt++)
                        mma_f16(acc[mt][nt], a[mt], b[nt]);
            }
        }

        // issue stage s+3
        if (s + 3 < NC) {
            const int ld = (s + 3) & 3;
            const int k0 = (s + 3) * 32;
#pragma unroll
            for (int i = 0; i < 2; i++)
                cpa16(a_dst0 + ld * STG_B + i * 16, arow + k0 + akh + i * 8);
#pragma unroll
            for (int i = 0; i < 2; i++)
                cpa16(b_dst0 + ld * STG_B + i * 128, brow + (size_t)(k0 + bk) * ldb + i * 64);
        }
        CP_COMMIT();
        st = (st + 1) & 3;
    }

    // ---- epilogue
    float spv = (MODE == 0) ? sp[0] : 0.f;
#pragma unroll
    for (int mt = 0; mt < 4; mt++) {
        int row = m0 + warp_m * 64 + mt * 16 + r;
#pragma unroll
        for (int hf = 0; hf < 2; hf++) {
            int rw = row + hf * 8;
            float rs0 = 0.f;
            if (MODE == 0) rs0 = spv * g_rnorm[rw];
#pragma unroll
            for (int nt = 0; nt < 4; nt++) {
                int col = n0 + warp_n * 32 + nt * 8 + 2 * t;
                float v0 = acc[mt][nt][hf * 2 + 0];
                float v1 = acc[mt][nt][hf * 2 + 1];
                if (MODE == 0) {
                    v0 *= rs0 * g_cinv[col];
                    v1 *= rs0 * g_cinv[col + 1];
                    *(float2*)(g_logits + (size_t)rw * 256 + col) = make_float2(v0, v1);
                } else if (MODE == 1) {
                    __half* orow = g_slot_h + (((size_t)z << 8) + rw) * 1024;
                    *(__half2*)(orow + col) = __floats2half2_rn(v0, v1);
                } else if (MODE == 2) {
                    v0 += X2[(z << 8) + col];
                    v1 += X2[(z << 8) + col + 1];
                    v0 = 0.5f * v0 * (1.f + erff(v0 * 0.70710678118654752f));
                    v1 = 0.5f * v1 * (1.f + erff(v1 * 0.70710678118654752f));
                    __half* orow = g_hh + (((size_t)z << 10) + rw) * 256;
                    *(__half2*)(orow + col) = __floats2half2_rn(v0, v1);
                } else if (MODE == 3) {
                    v0 += X2[(z << 10) + col];
                    v1 += X2[(z << 10) + col + 1];
                    int rr = ((rw >> 4) << 8) + (z << 4) + (rw & 15);
                    __half* orow = g_slot_h + (size_t)rr * 1024;
                    *(__half2*)(orow + col) = __floats2half2_rn(v0, v1);
                } else {
                    *(float2*)(Cout + (((size_t)z << 8) + rw) * 1024 + col) = make_float2(v0, v1);
                }
            }
        }
    }
}

// ---------------- launch --------------------------------------------------------
static const int GEMM_SMEM = 4 * STG_B;   // 75,776 bytes -> 2 CTAs/SM

extern "C" void kernel_launch(void* const* d_in, const int* in_sizes, int n_in,
                              void* d_out, int out_size) {
    const float* x     = (const float*)d_in[0];
    const float* gamma = (const float*)d_in[1];
    const float* beta  = (const float*)d_in[2];
    const float* mu    = (const float*)d_in[3];
    const float* scale = (const float*)d_in[4];
    const float* w1    = (const float*)d_in[5];
    const float* b1    = (const float*)d_in[6];
    const float* w2    = (const float*)d_in[7];
    const float* b2    = (const float*)d_in[8];
    float* out = (float*)d_out;

    static cudaStream_t s1 = nullptr, s2 = nullptr, s3 = nullptr;
    static cudaEvent_t eA, e1, e2, e3, eG0a, eG0b, eG1a, eG1b, eG3b;
    static int init_done = 0;
    if (!init_done) {
        cudaStreamCreateWithFlags(&s1, cudaStreamNonBlocking);
        cudaStreamCreateWithFlags(&s2, cudaStreamNonBlocking);
        cudaStreamCreateWithFlags(&s3, cudaStreamNonBlocking);
        cudaEventCreateWithFlags(&eA,  cudaEventDisableTiming);
        cudaEventCreateWithFlags(&e1,  cudaEventDisableTiming);
        cudaEventCreateWithFlags(&e2,  cudaEventDisableTiming);
        cudaEventCreateWithFlags(&e3,  cudaEventDisableTiming);
        cudaEventCreateWithFlags(&eG0a, cudaEventDisableTiming);
        cudaEventCreateWithFlags(&eG0b, cudaEventDisableTiming);
        cudaEventCreateWithFlags(&eG1a, cudaEventDisableTiming);
        cudaEventCreateWithFlags(&eG1b, cudaEventDisableTiming);
        cudaEventCreateWithFlags(&eG3b, cudaEventDisableTiming);
        cudaFuncSetAttribute(gemm_h<0>, cudaFuncAttributeMaxDynamicSharedMemorySize, GEMM_SMEM);
        cudaFuncSetAttribute(gemm_h<1>, cudaFuncAttributeMaxDynamicSharedMemorySize, GEMM_SMEM);
        cudaFuncSetAttribute(gemm_h<2>, cudaFuncAttributeMaxDynamicSharedMemorySize, GEMM_SMEM);
        cudaFuncSetAttribute(gemm_h<3>, cudaFuncAttributeMaxDynamicSharedMemorySize, GEMM_SMEM);
        cudaFuncSetAttribute(gemm_h<4>, cudaFuncAttributeMaxDynamicSharedMemorySize, GEMM_SMEM);
        init_done = 1;
    }

    __half* mur_p; cudaGetSymbolAddress((void**)&mur_p, g_mur_h);
    __half* w1_p;  cudaGetSymbolAddress((void**)&w1_p,  g_w1_h);
    __half* w2_p;  cudaGetSymbolAddress((void**)&w2_p,  g_w2_h);

    // fork
    cudaEventRecord(eA, 0);
    cudaStreamWaitEvent(s1, eA, 0);
    cudaStreamWaitEvent(s2, eA, 0);
    cudaStreamWaitEvent(s3, eA, 0);

    // s1: weight conversions
    half_copy<<<NEXP * DD * HH / 8192, 256, 0, s1>>>(w1, w1_p);
    half_copy<<<NEXP * HH * DD / 8192, 256, 0, s1>>>(w2, w2_p);
    cudaEventRecord(e1, s1);

    // s2: fused mu prep (norms + fp16 convert)
    mu_prep<<<8, 256, 0, s2>>>(mu, mur_p);
    cudaEventRecord(e2, s2);

    // s0: ln first half, s3: second half
    ln_kernel<<<1024, 256>>>(x, gamma, beta, 0);
    ln_kernel<<<1024, 256, 0, s3>>>(x, gamma, beta, 1024);

    // G0 halves — each needs its ln half + mu prep
    cudaStreamWaitEvent(0, e2, 0);
    gemm_h<0><<<dim3(2, 64, 1), 256, GEMM_SMEM>>>(nullptr, nullptr, scale, 0);
    cudaEventRecord(eG0a, 0);
    cudaStreamWaitEvent(s3, e2, 0);
    gemm_h<0><<<dim3(2, 64, 1), 256, GEMM_SMEM, s3>>>(nullptr, nullptr, scale, 64);
    cudaEventRecord(eG0b, s3);

    // combine (s2) after both logits halves
    cudaStreamWaitEvent(s2, eG0a, 0);
    cudaStreamWaitEvent(s2, eG0b, 0);
    combine_kernel<<<NTOK / 8, dim3(32, 8), 0, s2>>>();
    cudaEventRecord(e3, s2);

    // dispatch + G1 per batch half
    dispatch_kernel<<<dim3(8, 32), 256>>>(0);
    gemm_h<1><<<dim3(8, 2, 32), 256, GEMM_SMEM>>>(nullptr, nullptr, nullptr, 0);
    cudaEventRecord(eG1a, 0);

    dispatch_kernel<<<dim3(8, 32), 256, 0, s3>>>(32);
    gemm_h<1><<<dim3(8, 2, 32), 256, GEMM_SMEM, s3>>>(nullptr, nullptr, nullptr, 32);
    cudaEventRecord(eG1b, s3);

    // G2/G3 per expert half; each needs ALL of G1 + weights
    cudaStreamWaitEvent(0, e1, 0);
    cudaStreamWaitEvent(0, eG1b, 0);
    gemm_h<2><<<dim3(2, 8, 8), 256, GEMM_SMEM>>>(b1, nullptr, nullptr, 0);
    gemm_h<3><<<dim3(8, 8, 8), 256, GEMM_SMEM>>>(b2, nullptr, nullptr, 0);

    cudaStreamWaitEvent(s3, e1, 0);
    cudaStreamWaitEvent(s3, eG1a, 0);
    gemm_h<2><<<dim3(2, 8, 8), 256, GEMM_SMEM, s3>>>(b1, nullptr, nullptr, 8);
    gemm_h<3><<<dim3(8, 8, 8), 256, GEMM_SMEM, s3>>>(b2, nullptr, nullptr, 8);
    cudaEventRecord(eG3b, s3);

    // G4 after all slot_out + combine
    cudaStreamWaitEvent(0, eG3b, 0);
    cudaStreamWaitEvent(0, e3, 0);
    gemm_h<4><<<dim3(8, 2, 64), 256, GEMM_SMEM>>>(nullptr, out, nullptr, 0);
}

// round 16
// speedup vs baseline: 1.1147x; 1.0534x over previous
#include <cuda_runtime.h>
#include <cuda_fp16.h>
#include <math.h>
#include <stdint.h>

#define NTOK 16384
#define DD   1024
#define CC   256
#define BATCH 64
#define NSEQ 256
#define NEXP 16
#define HH   256

// ---------------- scratch ----------------------------------------------------
__device__ __half g_xn_h[NTOK * DD];
__device__ float  g_rnorm[NTOK];
__device__ float  g_cinv[CC];
__device__ float  g_logits[NTOK * CC];
__device__ __half g_dispT_h[BATCH * CC * NSEQ];
__device__ __half g_comb_h[NTOK * CC];
__device__ __half g_slot_h[BATCH * CC * DD];
__device__ __half g_hh[NEXP * 1024 * HH];
__device__ __half g_mur_h[DD * CC];
__device__ __half g_w1_h[NEXP * DD * HH];
__device__ __half g_w2_h[NEXP * HH * DD];

// ---------------- helpers ----------------------------------------------------
__device__ __forceinline__ uint32_t smem_u32(const void* p) {
    uint32_t a;
    asm("{ .reg .u64 t; cvta.to.shared.u64 t, %1; cvt.u32.u64 %0, t; }" : "=r"(a) : "l"(p));
    return a;
}
__device__ __forceinline__ void cpa16(uint32_t dst, const void* src) {
    asm volatile("cp.async.cg.shared.global [%0], [%1], 16;" :: "r"(dst), "l"(src));
}
#define CP_COMMIT() asm volatile("cp.async.commit_group;" ::: "memory")
#define CP_WAIT2()  asm volatile("cp.async.wait_group 2;" ::: "memory")

__device__ __forceinline__ void ldsm4(uint32_t* r, uint32_t addr) {
    asm volatile("ldmatrix.sync.aligned.m8n8.x4.shared.b16 {%0,%1,%2,%3}, [%4];"
                 : "=r"(r[0]), "=r"(r[1]), "=r"(r[2]), "=r"(r[3]) : "r"(addr));
}
__device__ __forceinline__ void ldsm4t(uint32_t* r, uint32_t addr) {
    asm volatile("ldmatrix.sync.aligned.m8n8.x4.trans.shared.b16 {%0,%1,%2,%3}, [%4];"
                 : "=r"(r[0]), "=r"(r[1]), "=r"(r[2]), "=r"(r[3]) : "r"(addr));
}
__device__ __forceinline__ void mma_f16(float* d, const uint32_t* a, const uint32_t* b) {
    asm volatile(
        "mma.sync.aligned.m16n8k16.row.col.f32.f16.f16.f32 "
        "{%0,%1,%2,%3}, {%4,%5,%6,%7}, {%8,%9}, {%0,%1,%2,%3};"
        : "+f"(d[0]), "+f"(d[1]), "+f"(d[2]), "+f"(d[3])
        : "r"(a[0]), "r"(a[1]), "r"(a[2]), "r"(a[3]), "r"(b[0]), "r"(b[1]));
}

// ---------------- fp32 -> fp16 conversion (MLP 8) ------------------------------
__global__ void half_copy(const float* __restrict__ src, __half* __restrict__ dst) {
    int i = blockIdx.x * 2048 + threadIdx.x;
    float4 v[8];
#pragma unroll
    for (int j = 0; j < 8; j++) v[j] = ((const float4*)src)[i + j * 256];
#pragma unroll
    for (int j = 0; j < 8; j++) {
        int o = i + j * 256;
        ((__half2*)dst)[2 * o]     = __floats2half2_rn(v[j].x, v[j].y);
        ((__half2*)dst)[2 * o + 1] = __floats2half2_rn(v[j].z, v[j].w);
    }
}

// ---------------- mu column norms ----------------------------------------------
__global__ void munorm_kernel(const float* __restrict__ mu) {
    int c = blockIdx.x, tid = threadIdx.x;
    float s = 0.f;
    for (int d = tid; d < DD; d += 256) {
        float a = mu[(size_t)d * CC + c];
        s += a * a;
    }
    __shared__ float r[256];
    r[tid] = s; __syncthreads();
    for (int o = 128; o > 0; o >>= 1) {
        if (tid < o) r[tid] += r[tid + o];
        __syncthreads();
    }
    if (tid == 0) g_cinv[c] = 1.f / fmaxf(sqrtf(r[0]), 1e-12f);
}

// ---------------- LayerNorm: warp per token, MLP 8 -----------------------------
__global__ void ln_kernel(const float* __restrict__ x,
                          const float* __restrict__ gamma,
                          const float* __restrict__ beta, int off) {
    int lane = threadIdx.x & 31;
    int t = (blockIdx.x + off) * 8 + (threadIdx.x >> 5);
    const float4* xr = (const float4*)(x + (size_t)t * DD);

    float4 v[8];
#pragma unroll
    for (int j = 0; j < 8; j++) v[j] = xr[lane + 32 * j];

    float s = 0.f, ss = 0.f;
#pragma unroll
    for (int j = 0; j < 8; j++) {
        s  += v[j].x + v[j].y + v[j].z + v[j].w;
        ss += v[j].x * v[j].x + v[j].y * v[j].y + v[j].z * v[j].z + v[j].w * v[j].w;
    }
    for (int o = 16; o > 0; o >>= 1) {
        s  += __shfl_xor_sync(0xffffffffu, s, o);
        ss += __shfl_xor_sync(0xffffffffu, ss, o);
    }
    float mean = s * (1.f / DD);
    float var  = ss * (1.f / DD) - mean * mean;
    float rstd = rsqrtf(var + 1e-5f);

    __half2* yr = (__half2*)(g_xn_h + (size_t)t * DD);
    float s2 = 0.f;
#pragma unroll
    for (int j = 0; j < 8; j++) {
        int i = lane + 32 * j;
        float4 g = ((const float4*)gamma)[i];
        float4 b = ((const float4*)beta)[i];
        __half2 h01 = __floats2half2_rn((v[j].x - mean) * rstd * g.x + b.x,
                                        (v[j].y - mean) * rstd * g.y + b.y);
        __half2 h23 = __floats2half2_rn((v[j].z - mean) * rstd * g.z + b.z,
                                        (v[j].w - mean) * rstd * g.w + b.w);
        yr[2 * i] = h01; yr[2 * i + 1] = h23;
        float2 f01 = __half22float2(h01), f23 = __half22float2(h23);
        s2 += f01.x * f01.x + f01.y * f01.y + f23.x * f23.x + f23.y * f23.y;
    }
    for (int o = 16; o > 0; o >>= 1) s2 += __shfl_xor_sync(0xffffffffu, s2, o);
    if (lane == 0) g_rnorm[t] = 1.f / fmaxf(sqrtf(s2), 1e-12f);
}

// ---------------- combine softmax ----------------------------------------------
__global__ void combine_kernel() {
    int row = blockIdx.x * 8 + threadIdx.y;
    int lane = threadIdx.x;
    const float* lr = g_logits + (size_t)row * CC;
    float v[8]; float mx = -1e30f;
#pragma unroll
    for (int j = 0; j < 8; j++) { v[j] = lr[lane + 32 * j]; mx = fmaxf(mx, v[j]); }
    for (int o = 16; o > 0; o >>= 1) mx = fmaxf(mx, __shfl_xor_sync(0xffffffffu, mx, o));
    float s = 0.f;
#pragma unroll
    for (int j = 0; j < 8; j++) { v[j] = __expf(v[j] - mx); s += v[j]; }
    for (int o = 16; o > 0; o >>= 1) s += __shfl_xor_sync(0xffffffffu, s, o);
    float inv = 1.f / s;
    __half* cr = g_comb_h + (size_t)row * CC;
#pragma unroll
    for (int j = 0; j < 8; j++) cr[lane + 32 * j] = __float2half_rn(v[j] * inv);
}

// ---------------- dispatch softmax; transposed fp16 output ----------------------
__global__ void dispatch_kernel(int boff) {
    int b = blockIdx.y + boff, c0 = blockIdx.x * 32, tid = threadIdx.x;
    int c = tid & 31, nb = tid >> 5;
    __shared__ float tile[256][33];
    __shared__ float pred[8][32];
    __shared__ float colv[32];

    const size_t base = ((size_t)b * NSEQ) * CC + c0;
#pragma unroll
    for (int it = 0; it < 32; it++) {
        int n = nb + 8 * it;
        tile[n][c] = g_logits[base + (size_t)n * CC + c];
    }
    __syncthreads();
    float mx = -1e30f;
#pragma unroll
    for (int j = 0; j < 32; j++) mx = fmaxf(mx, tile[nb * 32 + j][c]);
    pred[nb][c] = mx; __syncthreads();
    if (nb == 0) {
        float m = pred[0][c];
#pragma unroll
        for (int j = 1; j < 8; j++) m = fmaxf(m, pred[j][c]);
        colv[c] = m;
    }
    __syncthreads();
    float cm = colv[c];
    float s = 0.f;
#pragma unroll
    for (int j = 0; j < 32; j++) {
        float e = __expf(tile[nb * 32 + j][c] - cm);
        tile[nb * 32 + j][c] = e; s += e;
    }
    pred[nb][c] = s; __syncthreads();
    if (nb == 0) {
        float t = 0.f;
#pragma unroll
        for (int j = 0; j < 8; j++) t += pred[j][c];
        colv[c] = 1.f / t;
    }
    __syncthreads();
    int lane2 = tid & 31, cg = tid >> 5;
#pragma unroll
    for (int cc2 = 0; cc2 < 4; cc2++) {
        int cl = cg + 8 * cc2;
        float inv = colv[cl];
        size_t ob = ((size_t)b * CC + c0 + cl) * NSEQ;
#pragma unroll
        for (int itn = 0; itn < 8; itn++) {
            int n = lane2 + 32 * itn;
            g_dispT_h[ob + n] = __float2half_rn(tile[n][cl] * inv);
        }
    }
}

// ---------------- fp16 mma GEMM, CTA 128x128, occ 2, cp.async 4-stage -----------
// Mainloop order: wait -> sync -> COMPUTE -> issue s+3 -> commit  (R12-proven)
#define STG_B 18944
#define B_OFF 10240

template <int MODE>
__global__ void __launch_bounds__(256, 2) gemm_h(const float* __restrict__ X2,
                                                 float* __restrict__ Cout,
                                                 const float* __restrict__ sp,
                                                 int off) {
    constexpr int Kx  = (MODE == 0 || MODE == 2) ? 1024 : 256;
    constexpr int ldb = (MODE == 0 || MODE == 2) ? 256 : 1024;
    constexpr int lda = (MODE == 0 || MODE == 2) ? 1024 : 256;
    constexpr int NC  = Kx / 32;

    extern __shared__ __half sm[];
    const uint32_t sb = smem_u32(sm);
    const int tid = threadIdx.x, wid = tid >> 5, lane = tid & 31;
    const int warp_m = wid & 1, warp_n = wid >> 1;
    const int r = lane >> 2, t = lane & 3;
    const int z  = (MODE == 0) ? 0 : (blockIdx.z + ((MODE == 4) ? 0 : off));
    const int m0 = ((MODE == 0) ? (blockIdx.y + off) : blockIdx.y) * 128;
    const int n0 = blockIdx.x * 128;

    const __half* Abase;
    const __half* Bbase;
    if (MODE == 0)      { Abase = g_xn_h + (size_t)m0 * 1024;                        Bbase = g_mur_h; }
    else if (MODE == 1) { Abase = g_dispT_h + ((size_t)z << 16) + (size_t)m0 * 256;  Bbase = g_xn_h + ((size_t)z << 18); }
    else if (MODE == 2) { Abase = g_slot_h;                                          Bbase = g_w1_h + ((size_t)z << 18); }
    else if (MODE == 3) { Abase = g_hh + ((size_t)z << 18) + (size_t)m0 * 256;       Bbase = g_w2_h + ((size_t)z << 18); }
    else                { Abase = g_comb_h + ((size_t)z << 16) + (size_t)m0 * 256;   Bbase = g_slot_h + ((size_t)z << 18); }

    const int am  = tid >> 1;
    const int akh = (tid & 1) * 16;
    const int bk  = tid >> 3;
    const int bn8 = (tid & 7) * 8;
    const __half* arow;
    if (MODE == 2) {
        int g = m0 + am;
        arow = g_slot_h + (size_t)(((g >> 4) << 8) + (z << 4) + (g & 15)) * 1024;
    } else {
        arow = Abase + (size_t)am * lda;
    }
    const __half* brow = Bbase + n0 + bn8;
    const uint32_t a_dst0 = sb + am * 80 + akh * 2;
    const uint32_t b_dst0 = sb + B_OFF + bk * 272 + bn8 * 2;

    float acc[4][4][4];
#pragma unroll
    for (int mt = 0; mt < 4; mt++)
#pragma unroll
        for (int nt = 0; nt < 4; nt++)
#pragma unroll
            for (int q = 0; q < 4; q++) acc[mt][nt][q] = 0.f;

    // prologue: stages 0..2
#pragma unroll
    for (int stg = 0; stg < 3; stg++) {
        const int k0 = stg * 32;
#pragma unroll
        for (int i = 0; i < 2; i++)
            cpa16(a_dst0 + stg * STG_B + i * 16, arow + k0 + akh + i * 8);
#pragma unroll
        for (int i = 0; i < 2; i++)
            cpa16(b_dst0 + stg * STG_B + i * 128, brow + (size_t)(k0 + bk) * ldb + i * 64);
        CP_COMMIT();
    }

    int st = 0;
#pragma unroll 1
    for (int s = 0; s < NC; s++) {
        CP_WAIT2();
        __syncthreads();

        // compute stage st
        {
            const uint32_t base = sb + st * STG_B;
            const uint32_t a_ld = base + (warp_m * 64 + (lane & 15)) * 80 + (lane >> 4) * 16;
            const uint32_t b_ld = base + B_OFF + (((lane >> 3) & 1) * 8 + (lane & 7)) * 272
                                  + (warp_n * 32 + (lane >> 4) * 8) * 2;
#pragma unroll
            for (int ks = 0; ks < 2; ks++) {
                uint32_t a[4][4], b[4][2];
#pragma unroll
                for (int mt = 0; mt < 4; mt++)
                    ldsm4(a[mt], a_ld + mt * (16 * 80) + ks * 32);
#pragma unroll
                for (int ntp = 0; ntp < 2; ntp++) {
                    uint32_t bbf[4];
                    ldsm4t(bbf, b_ld + ks * (16 * 272) + ntp * 32);
                    b[2 * ntp][0] = bbf[0]; b[2 * ntp][1] = bbf[1];
                    b[2 * ntp + 1][0] = bbf[2]; b[2 * ntp + 1][1] = bbf[3];
                }
#pragma unroll
                for (int mt = 0; mt < 4; mt++)
#pragma unroll
                    for (int nt = 0; nt < 4; nt++)
                        mma_f16(acc[mt][nt], a[mt], b[nt]);
            }
        }

        // issue stage s+3
        if (s + 3 < NC) {
            const int ld = (s + 3) & 3;
            const int k0 = (s + 3) * 32;
#pragma unroll
            for (int i = 0; i < 2; i++)
                cpa16(a_dst0 + ld * STG_B + i * 16, arow + k0 + akh + i * 8);
#pragma unroll
            for (int i = 0; i < 2; i++)
                cpa16(b_dst0 + ld * STG_B + i * 128, brow + (size_t)(k0 + bk) * ldb + i * 64);
        }
        CP_COMMIT();
        st = (st + 1) & 3;
    }

    // ---- epilogue
    float spv = (MODE == 0) ? sp[0] : 0.f;
#pragma unroll
    for (int mt = 0; mt < 4; mt++) {
        int row = m0 + warp_m * 64 + mt * 16 + r;
#pragma unroll
        for (int hf = 0; hf < 2; hf++) {
            int rw = row + hf * 8;
            float rs0 = 0.f;
            if (MODE == 0) rs0 = spv * g_rnorm[rw];
#pragma unroll
            for (int nt = 0; nt < 4; nt++) {
                int col = n0 + warp_n * 32 + nt * 8 + 2 * t;
                float v0 = acc[mt][nt][hf * 2 + 0];
                float v1 = acc[mt][nt][hf * 2 + 1];
                if (MODE == 0) {
                    v0 *= rs0 * g_cinv[col];
                    v1 *= rs0 * g_cinv[col + 1];
                    *(float2*)(g_logits + (size_t)rw * 256 + col) = make_float2(v0, v1);
                } else if (MODE == 1) {
                    __half* orow = g_slot_h + (((size_t)z << 8) + rw) * 1024;
                    *(__half2*)(orow + col) = __floats2half2_rn(v0, v1);
                } else if (MODE == 2) {
                    v0 += X2[(z << 8) + col];
                    v1 += X2[(z << 8) + col + 1];
                    v0 = 0.5f * v0 * (1.f + erff(v0 * 0.70710678118654752f));
                    v1 = 0.5f * v1 * (1.f + erff(v1 * 0.70710678118654752f));
                    __half* orow = g_hh + (((size_t)z << 10) + rw) * 256;
                    *(__half2*)(orow + col) = __floats2half2_rn(v0, v1);
                } else if (MODE == 3) {
                    v0 += X2[(z << 10) + col];
                    v1 += X2[(z << 10) + col + 1];
                    int rr = ((rw >> 4) << 8) + (z << 4) + (rw & 15);
                    __half* orow = g_slot_h + (size_t)rr * 1024;
                    *(__half2*)(orow + col) = __floats2half2_rn(v0, v1);
                } else {
                    *(float2*)(Cout + (((size_t)z << 8) + rw) * 1024 + col) = make_float2(v0, v1);
                }
            }
        }
    }
}

// ---------------- launch --------------------------------------------------------
static const int GEMM_SMEM = 4 * STG_B;   // 75,776 bytes -> 2 CTAs/SM

extern "C" void kernel_launch(void* const* d_in, const int* in_sizes, int n_in,
                              void* d_out, int out_size) {
    const float* x     = (const float*)d_in[0];
    const float* gamma = (const float*)d_in[1];
    const float* beta  = (const float*)d_in[2];
    const float* mu    = (const float*)d_in[3];
    const float* scale = (const float*)d_in[4];
    const float* w1    = (const float*)d_in[5];
    const float* b1    = (const float*)d_in[6];
    const float* w2    = (const float*)d_in[7];
    const float* b2    = (const float*)d_in[8];
    float* out = (float*)d_out;

    static cudaStream_t s1 = nullptr, s2 = nullptr, s3 = nullptr;
    static cudaEvent_t eA, e1, e2, e3, eG0a, eG0b, eG1a, eG1b, eG3b;
    static int init_done = 0;
    if (!init_done) {
        cudaStreamCreateWithFlags(&s1, cudaStreamNonBlocking);
        cudaStreamCreateWithFlags(&s2, cudaStreamNonBlocking);
        cudaStreamCreateWithFlags(&s3, cudaStreamNonBlocking);
        cudaEventCreateWithFlags(&eA,  cudaEventDisableTiming);
        cudaEventCreateWithFlags(&e1,  cudaEventDisableTiming);
        cudaEventCreateWithFlags(&e2,  cudaEventDisableTiming);
        cudaEventCreateWithFlags(&e3,  cudaEventDisableTiming);
        cudaEventCreateWithFlags(&eG0a, cudaEventDisableTiming);
        cudaEventCreateWithFlags(&eG0b, cudaEventDisableTiming);
        cudaEventCreateWithFlags(&eG1a, cudaEventDisableTiming);
        cudaEventCreateWithFlags(&eG1b, cudaEventDisableTiming);
        cudaEventCreateWithFlags(&eG3b, cudaEventDisableTiming);
        cudaFuncSetAttribute(gemm_h<0>, cudaFuncAttributeMaxDynamicSharedMemorySize, GEMM_SMEM);
        cudaFuncSetAttribute(gemm_h<1>, cudaFuncAttributeMaxDynamicSharedMemorySize, GEMM_SMEM);
        cudaFuncSetAttribute(gemm_h<2>, cudaFuncAttributeMaxDynamicSharedMemorySize, GEMM_SMEM);
        cudaFuncSetAttribute(gemm_h<3>, cudaFuncAttributeMaxDynamicSharedMemorySize, GEMM_SMEM);
        cudaFuncSetAttribute(gemm_h<4>, cudaFuncAttributeMaxDynamicSharedMemorySize, GEMM_SMEM);
        init_done = 1;
    }

    __half* mur_p; cudaGetSymbolAddress((void**)&mur_p, g_mur_h);
    __half* w1_p;  cudaGetSymbolAddress((void**)&w1_p,  g_w1_h);
    __half* w2_p;  cudaGetSymbolAddress((void**)&w2_p,  g_w2_h);

    // fork
    cudaEventRecord(eA, 0);
    cudaStreamWaitEvent(s1, eA, 0);
    cudaStreamWaitEvent(s2, eA, 0);
    cudaStreamWaitEvent(s3, eA, 0);

    // s1: weight conversions
    half_copy<<<NEXP * DD * HH / 8192, 256, 0, s1>>>(w1, w1_p);
    half_copy<<<NEXP * HH * DD / 8192, 256, 0, s1>>>(w2, w2_p);
    cudaEventRecord(e1, s1);

    // s2: mu prep (parallel-enough pair; both done well inside ln's shadow)
    munorm_kernel<<<CC, 256, 0, s2>>>(mu);
    half_copy<<<DD * CC / 8192, 256, 0, s2>>>(mu, mur_p);
    cudaEventRecord(e2, s2);

    // s0: ln first half, s3: second half
    ln_kernel<<<1024, 256>>>(x, gamma, beta, 0);
    ln_kernel<<<1024, 256, 0, s3>>>(x, gamma, beta, 1024);

    // G0 halves — each needs its ln half + mu prep
    cudaStreamWaitEvent(0, e2, 0);
    gemm_h<0><<<dim3(2, 64, 1), 256, GEMM_SMEM>>>(nullptr, nullptr, scale, 0);
    cudaEventRecord(eG0a, 0);
    cudaStreamWaitEvent(s3, e2, 0);
    gemm_h<0><<<dim3(2, 64, 1), 256, GEMM_SMEM, s3>>>(nullptr, nullptr, scale, 64);
    cudaEventRecord(eG0b, s3);

    // combine (s2) after both logits halves
    cudaStreamWaitEvent(s2, eG0a, 0);
    cudaStreamWaitEvent(s2, eG0b, 0);
    combine_kernel<<<NTOK / 8, dim3(32, 8), 0, s2>>>();
    cudaEventRecord(e3, s2);

    // dispatch + G1 per batch half
    dispatch_kernel<<<dim3(8, 32), 256>>>(0);
    gemm_h<1><<<dim3(8, 2, 32), 256, GEMM_SMEM>>>(nullptr, nullptr, nullptr, 0);
    cudaEventRecord(eG1a, 0);

    dispatch_kernel<<<dim3(8, 32), 256, 0, s3>>>(32);
    gemm_h<1><<<dim3(8, 2, 32), 256, GEMM_SMEM, s3>>>(nullptr, nullptr, nullptr, 32);
    cudaEventRecord(eG1b, s3);

    // G2/G3 per expert half; each needs ALL of G1 + weights
    cudaStreamWaitEvent(0, e1, 0);
    cudaStreamWaitEvent(0, eG1b, 0);
    gemm_h<2><<<dim3(2, 8, 8), 256, GEMM_SMEM>>>(b1, nullptr, nullptr, 0);
    gemm_h<3><<<dim3(8, 8, 8), 256, GEMM_SMEM>>>(b2, nullptr, nullptr, 0);

    cudaStreamWaitEvent(s3, e1, 0);
    cudaStreamWaitEvent(s3, eG1a, 0);
    gemm_h<2><<<dim3(2, 8, 8), 256, GEMM_SMEM, s3>>>(b1, nullptr, nullptr, 8);
    gemm_h<3><<<dim3(8, 8, 8), 256, GEMM_SMEM, s3>>>(b2, nullptr, nullptr, 8);
    cudaEventRecord(eG3b, s3);

    // G4 after all slot_out + combine
    cudaStreamWaitEvent(0, eG3b, 0);
    cudaStreamWaitEvent(0, e3, 0);
    gemm_h<4><<<dim3(8, 2, 64), 256, GEMM_SMEM>>>(nullptr, out, nullptr, 0);
}